// round 5
// baseline (speedup 1.0000x reference)
#include <cuda_runtime.h>

// CRF forward scan, probability domain, TWO batches per CTA in the SAME threads.
//   Both scans share the register-resident E = exp(trans) (split across thread
//   pairs: tid = 2*i + h holds E[i][h*64..h*64+64) as 32 f32x2 regs).
//   The two chains are independent -> latency of one hides behind issue of the
//   other; ONE __syncthreads covers both batch-steps.
//   Renorm: exact power-of-two scale from previous step's per-warp maxima.

#define KDIM 128
typedef unsigned long long u64;

__device__ __forceinline__ void fma2(u64& a, u64 x, u64 p) {
    asm("fma.rn.f32x2 %0, %1, %2, %0;" : "+l"(a) : "l"(x), "l"(p));
}
__device__ __forceinline__ u64 add2(u64 a, u64 b) {
    u64 r; asm("add.rn.f32x2 %0, %1, %2;" : "=l"(r) : "l"(a), "l"(b)); return r;
}
__device__ __forceinline__ u64 pack2(float lo, float hi) {
    u64 r; asm("mov.b64 %0, {%1, %2};" : "=l"(r) : "f"(lo), "f"(hi)); return r;
}
__device__ __forceinline__ float unpack_sum(u64 a) {
    float lo, hi; asm("mov.b64 {%0, %1}, %2;" : "=f"(lo), "=f"(hi) : "l"(a));
    return lo + hi;
}

__global__ __launch_bounds__(256, 1)
void crf_fwd_kernel(const float* __restrict__ y,
                    const float* __restrict__ mask,
                    const float* __restrict__ trans,
                    float* __restrict__ out,
                    int T, int B) {
    const int b0   = blockIdx.x * 2;
    const int b1   = b0 + 1;
    const int b1v  = (b1 < B) ? b1 : (B - 1);   // safe pointer for odd B
    const int tid  = threadIdx.x;
    const int i    = tid >> 1;          // state 0..127
    const int h    = tid & 1;           // j-half
    const int lane = tid & 31;
    const int warp = tid >> 5;          // 0..7 ; warp holds states 16w..16w+15 (x2)

    __shared__ __align__(16) float    pA[2][KDIM], pB[2][KDIM];
    __shared__ __align__(16) unsigned wmA[2][8],  wmB[2][8];
    __shared__ float redA[8], redB[8];
    __shared__ int   lenA_sh, lenB_sh;

    // ---- one-time: half E-row as 32 f32x2 regs (shared by both batches) ----
    u64 E2[32];
    {
        const float4* t4 =
            reinterpret_cast<const float4*>(trans + (size_t)i * KDIM + (h << 6));
        #pragma unroll
        for (int q = 0; q < 16; q++) {
            float4 v = t4[q];
            E2[2*q]   = pack2(expf(v.x), expf(v.y));
            E2[2*q+1] = pack2(expf(v.z), expf(v.w));
        }
    }

    // ---- init ----
    if (tid == 0) { lenA_sh = 0; lenB_sh = 0; }
    if (tid < KDIM) {
        float v = (tid == 2) ? 1.0f : 0.0f;     // SOS_IDX = 2
        pA[0][tid] = v;  pB[0][tid] = v;
    }
    if (tid < 8)               wmA[0][tid]     = 0x3f800000u;
    else if (tid < 16)         wmB[0][tid - 8] = 0x3f800000u;
    __syncthreads();
    {
        const float* mA = mask + (size_t)b0  * T;
        const float* mB = mask + (size_t)b1v * T;
        int cA = 0, cB = 0;
        for (int t = tid; t < T; t += 256) {
            cA += (mA[t] != 0.0f);
            cB += (mB[t] != 0.0f);
        }
        cA = __reduce_add_sync(0xffffffffu, cA);
        cB = __reduce_add_sync(0xffffffffu, cB);
        if (lane == 0) { atomicAdd(&lenA_sh, cA); atomicAdd(&lenB_sh, cB); }
    }
    __syncthreads();
    const int lenA = lenA_sh, lenB = lenB_sh;
    const int maxlen = max(lenA, lenB);

    // ---- y prefetch pipelines (3 deep), pair threads load same element ----
    const float* ybA = y + (size_t)b0  * T * KDIM + i;
    const float* ybB = y + (size_t)b1v * T * KDIM + i;
    float eyA = (maxlen > 0) ? __expf(ybA[0]) : 1.0f;
    float eyB = (maxlen > 0) ? __expf(ybB[0]) : 1.0f;
    float y1A = (1 < T) ? ybA[KDIM]     : 0.0f;
    float y1B = (1 < T) ? ybB[KDIM]     : 0.0f;
    float y2A = (2 < T) ? ybA[2*KDIM]   : 0.0f;
    float y2B = (2 < T) ? ybB[2*KDIM]   : 0.0f;

    float sA = (i == 2) ? 1.0f : 0.0f;
    float sB = sA;
    int eaccA = 0, eaccB = 0, cur = 0;

    for (int t = 0; t < maxlen; t++) {
        // Z_t for both batches from previous step's per-warp maxima
        uint4 wa0 = *reinterpret_cast<const uint4*>(&wmA[cur][0]);
        uint4 wa1 = *reinterpret_cast<const uint4*>(&wmA[cur][4]);
        uint4 wb0 = *reinterpret_cast<const uint4*>(&wmB[cur][0]);
        uint4 wb1 = *reinterpret_cast<const uint4*>(&wmB[cur][4]);
        unsigned mAb = max(max(max(wa0.x, wa0.y), max(wa0.z, wa0.w)),
                           max(max(wa1.x, wa1.y), max(wa1.z, wa1.w)));
        unsigned mBb = max(max(max(wb0.x, wb0.y), max(wb0.z, wb0.w)),
                           max(max(wb1.x, wb1.y), max(wb1.z, wb1.w)));
        int EeA = (int)(mAb >> 23), EeB = (int)(mBb >> 23);
        float rzA = __uint_as_float((unsigned)(254 - EeA) << 23);
        float rzB = __uint_as_float((unsigned)(254 - EeB) << 23);
        if (t < lenA) eaccA += EeA - 127;
        if (t < lenB) eaccB += EeB - 127;

        // two independent half-matvecs (16 LDS.128 + 32 fma.f32x2 each)
        const ulonglong2* pa = reinterpret_cast<const ulonglong2*>(pA[cur] + (h << 6));
        const ulonglong2* pb = reinterpret_cast<const ulonglong2*>(pB[cur] + (h << 6));
        u64 aA0=0, aA1=0, aA2=0, aA3=0;
        u64 aB0=0, aB1=0, aB2=0, aB3=0;
        #pragma unroll
        for (int q = 0; q < 4; q++) {
            ulonglong2 va0 = pa[4*q+0], va1 = pa[4*q+1];
            ulonglong2 va2 = pa[4*q+2], va3 = pa[4*q+3];
            ulonglong2 vb0 = pb[4*q+0], vb1 = pb[4*q+1];
            ulonglong2 vb2 = pb[4*q+2], vb3 = pb[4*q+3];
            fma2(aA0, E2[8*q+0], va0.x);  fma2(aB0, E2[8*q+0], vb0.x);
            fma2(aA1, E2[8*q+1], va0.y);  fma2(aB1, E2[8*q+1], vb0.y);
            fma2(aA2, E2[8*q+2], va1.x);  fma2(aB2, E2[8*q+2], vb1.x);
            fma2(aA3, E2[8*q+3], va1.y);  fma2(aB3, E2[8*q+3], vb1.y);
            fma2(aA0, E2[8*q+4], va2.x);  fma2(aB0, E2[8*q+4], vb2.x);
            fma2(aA1, E2[8*q+5], va2.y);  fma2(aB1, E2[8*q+5], vb2.y);
            fma2(aA2, E2[8*q+6], va3.x);  fma2(aB2, E2[8*q+6], vb3.x);
            fma2(aA3, E2[8*q+7], va3.y);  fma2(aB3, E2[8*q+7], vb3.y);
        }
        float qA = unpack_sum(add2(add2(aA0, aA1), add2(aA2, aA3)));
        float qB = unpack_sum(add2(add2(aB0, aB1), add2(aB2, aB3)));
        qA += __shfl_xor_sync(0xffffffffu, qA, 1);   // combine j-halves
        qB += __shfl_xor_sync(0xffffffffu, qB, 1);
        float snA = qA * eyA * rzA;                  // >= 0, never overflows
        float snB = qB * eyB * rzB;
        sA = (t < lenA) ? snA : sA;                  // carry past sequence end
        sB = (t < lenB) ? snB : sB;

        unsigned wvA = __reduce_max_sync(0xffffffffu, __float_as_uint(sA));
        unsigned wvB = __reduce_max_sync(0xffffffffu, __float_as_uint(sB));
        if (lane == 0) { wmA[cur^1][warp] = wvA; wmB[cur^1][warp] = wvB; }
        if (h == 0)    { pA[cur^1][i] = sA;      pB[cur^1][i] = sB; }

        // rotate y pipelines (off critical path)
        eyA = __expf(y1A);  y1A = y2A;
        eyB = __expf(y1B);  y1B = y2B;
        int tf = t + 3;
        y2A = (tf < T) ? ybA[(size_t)tf * KDIM] : 0.0f;
        y2B = (tf < T) ? ybB[(size_t)tf * KDIM] : 0.0f;

        __syncthreads();
        cur ^= 1;
    }

    // ---- finals: out[b] = log(sum_i s_i) + eacc*ln2  (states duplicated x2) ----
    float eA = sA, eB = sB;
    #pragma unroll
    for (int d = 16; d >= 1; d >>= 1) {
        eA += __shfl_xor_sync(0xffffffffu, eA, d);
        eB += __shfl_xor_sync(0xffffffffu, eB, d);
    }
    if (lane == 0) { redA[warp] = eA; redB[warp] = eB; }
    __syncthreads();
    if (tid == 0) {
        float totA = ((redA[0]+redA[1]) + (redA[2]+redA[3])) +
                     ((redA[4]+redA[5]) + (redA[6]+redA[7]));
        out[b0] = logf(totA * 0.5f) + (float)((double)eaccA * 0.6931471805599453);
        if (b1 < B) {
            float totB = ((redB[0]+redB[1]) + (redB[2]+redB[3])) +
                         ((redB[4]+redB[5]) + (redB[6]+redB[7]));
            out[b1] = logf(totB * 0.5f) + (float)((double)eaccB * 0.6931471805599453);
        }
    }
}

extern "C" void kernel_launch(void* const* d_in, const int* in_sizes, int n_in,
                              void* d_out, int out_size) {
    const float* y     = (const float*)d_in[0];   // (B, T, K) f32
    const float* mask  = (const float*)d_in[1];   // (B, T)    f32
    const float* trans = (const float*)d_in[2];   // (K, K)    f32
    float* out = (float*)d_out;                   // (B,)      f32

    const int B = out_size;                       // 64
    const int T = in_sizes[1] / B;                // 256

    crf_fwd_kernel<<<(B + 1) / 2, 256>>>(y, mask, trans, out, T, B);
}

// round 6
// speedup vs baseline: 2.5550x; 2.5550x over previous
#include <cuda_runtime.h>

// CRF forward scan, probability domain (scaled HMM forward).
// R2 frame (proven fastest): 1 CTA per batch, 128 threads, full E-row per
// thread in registers (64 f32x2). One __syncthreads per step.
// This round: 4 accumulators (shorter reduce tree), renorm bookkeeping every
// 2nd step with parity-double-buffered wmax (exact eacc accounting, lagged
// max only affects range: bounded < 2^41), pointer-increment y prefetch.

#define KDIM 128
typedef unsigned long long u64;

__device__ __forceinline__ void fma2(u64& a, u64 x, u64 p) {
    asm("fma.rn.f32x2 %0, %1, %2, %0;" : "+l"(a) : "l"(x), "l"(p));
}
__device__ __forceinline__ u64 add2(u64 a, u64 b) {
    u64 r; asm("add.rn.f32x2 %0, %1, %2;" : "=l"(r) : "l"(a), "l"(b)); return r;
}
__device__ __forceinline__ u64 pack2(float lo, float hi) {
    u64 r; asm("mov.b64 %0, {%1, %2};" : "=l"(r) : "f"(lo), "f"(hi)); return r;
}

__global__ __launch_bounds__(128, 1)
void crf_fwd_kernel(const float* __restrict__ y,
                    const float* __restrict__ mask,
                    const float* __restrict__ trans,
                    float* __restrict__ out,
                    int T) {
    const int b    = blockIdx.x;
    const int i    = threadIdx.x;      // 0..127 : output state
    const int lane = i & 31;
    const int warp = i >> 5;

    __shared__ __align__(16) float    pbuf[2][KDIM];
    __shared__ __align__(16) unsigned wmax[2][4];   // parity slots
    __shared__ float redf[4];
    __shared__ int   len_sh;

    // ---- one-time: E row = exp(trans[i][:]) as 64 packed f32x2 regs ----
    u64 E2[64];
    {
        const float4* t4 = reinterpret_cast<const float4*>(trans + (size_t)i * KDIM);
        #pragma unroll
        for (int q = 0; q < 32; q++) {
            float4 v = t4[q];
            E2[2*q]   = pack2(expf(v.x), expf(v.y));
            E2[2*q+1] = pack2(expf(v.z), expf(v.w));
        }
    }

    // ---- init state, renorm buffers, length ----
    if (i == 0) len_sh = 0;
    pbuf[0][i] = (i == 2) ? 1.0f : 0.0f;            // SOS_IDX = 2
    if (i < 8) wmax[i >> 2][i & 3] = 0x3f800000u;   // both slots: max(s_0)=1
    __syncthreads();
    {
        const float* mb = mask + (size_t)b * T;
        int cnt = 0;
        for (int t = i; t < T; t += KDIM) cnt += (mb[t] != 0.0f);
        cnt = __reduce_add_sync(0xffffffffu, cnt);
        if (lane == 0) atomicAdd(&len_sh, cnt);
    }
    __syncthreads();
    const int len = len_sh;

    // ---- y prefetch pipeline (3 deep), pointer-increment ----
    const float* yb = y + (size_t)b * T * KDIM + i;
    const float* yp = yb + 3 * KDIM;                // next address to fetch
    const float* yend = yb + (size_t)T * KDIM;
    float ey = 0.0f, y1 = 0.0f, y2 = 0.0f;
    if (len > 0) ey = __expf(yb[0]);
    if (1 < T)   y1 = yb[KDIM];
    if (2 < T)   y2 = yb[2 * KDIM];

    int cur  = 0;
    int eacc = 0;

    for (int t = 0; t < len; t++) {
        // rz from lagged max (parity slot written at the last even step < t;
        // always separated from this read by >=1 barrier). Off critical path.
        const int slotR = ((t - 1) >> 1) & 1;
        uint4 wm4 = *reinterpret_cast<const uint4*>(wmax[slotR]);
        unsigned mbits = max(max(wm4.x, wm4.y), max(wm4.z, wm4.w));
        int Ee   = (int)(mbits >> 23);
        float rz = __uint_as_float((unsigned)(254 - Ee) << 23);  // 2^(127-Ee)
        eacc    += Ee - 127;

        // matvec: q_i = sum_j E[i][j] * s_t[j]  (32x LDS.128 + 64x fma.f32x2)
        const ulonglong2* p2 = reinterpret_cast<const ulonglong2*>(pbuf[cur]);
        u64 a0 = 0, a1 = 0, a2 = 0, a3 = 0;
        #pragma unroll
        for (int q = 0; q < 8; q++) {
            ulonglong2 v0 = p2[4*q+0];
            ulonglong2 v1 = p2[4*q+1];
            ulonglong2 v2 = p2[4*q+2];
            ulonglong2 v3 = p2[4*q+3];
            fma2(a0, E2[8*q+0], v0.x);
            fma2(a1, E2[8*q+1], v0.y);
            fma2(a2, E2[8*q+2], v1.x);
            fma2(a3, E2[8*q+3], v1.y);
            fma2(a0, E2[8*q+4], v2.x);
            fma2(a1, E2[8*q+5], v2.y);
            fma2(a2, E2[8*q+6], v3.x);
            fma2(a3, E2[8*q+7], v3.y);
        }
        u64 aa = add2(add2(a0, a1), add2(a2, a3));
        float qlo, qhi;
        asm("mov.b64 {%0, %1}, %2;" : "=f"(qlo), "=f"(qhi) : "l"(aa));
        float s = (qlo + qhi) * ey * rz;             // s >= 0 always

        // renorm bookkeeping every 2nd step only
        if (!(t & 1)) {
            unsigned wmv = __reduce_max_sync(0xffffffffu, __float_as_uint(s));
            if (lane == 0) wmax[(t >> 1) & 1][warp] = wmv;
        }
        pbuf[cur ^ 1][i] = s;

        // rotate y pipeline (off critical path)
        ey = __expf(y1);
        y1 = y2;
        y2 = (yp < yend) ? *yp : 0.0f;
        yp += KDIM;

        __syncthreads();
        cur ^= 1;
    }

    // ---- final: out[b] = log(sum_i s_i) + eacc*ln2 ----
    float e = pbuf[cur][i];
    e += __shfl_xor_sync(0xffffffffu, e, 16);
    e += __shfl_xor_sync(0xffffffffu, e, 8);
    e += __shfl_xor_sync(0xffffffffu, e, 4);
    e += __shfl_xor_sync(0xffffffffu, e, 2);
    e += __shfl_xor_sync(0xffffffffu, e, 1);
    if (lane == 0) redf[warp] = e;
    __syncthreads();
    if (i == 0) {
        float tot = (redf[0] + redf[1]) + (redf[2] + redf[3]);
        out[b] = logf(tot) + (float)((double)eacc * 0.6931471805599453);
    }
}

extern "C" void kernel_launch(void* const* d_in, const int* in_sizes, int n_in,
                              void* d_out, int out_size) {
    const float* y     = (const float*)d_in[0];   // (B, T, K) f32
    const float* mask  = (const float*)d_in[1];   // (B, T)    f32
    const float* trans = (const float*)d_in[2];   // (K, K)    f32
    float* out = (float*)d_out;                   // (B,)      f32

    const int B = out_size;                       // 64
    const int T = in_sizes[1] / B;                // 256

    crf_fwd_kernel<<<B, 128>>>(y, mask, trans, out, T);
}

// round 7
// speedup vs baseline: 2.8172x; 1.1026x over previous
#include <cuda_runtime.h>

// CRF forward scan, probability domain (scaled HMM forward).
// Champion R2 frame: 1 CTA/batch, 128 threads, full E-row per thread as 64
// packed f32x2 regs, 8 accumulators, every-step power-of-two renorm via
// REDUX.MAX, one __syncthreads per step.
// R7 micro-trims: ey*rz precomputed off-path; pbuf store issued before REDUX;
// pointer-increment y prefetch.

#define KDIM 128
typedef unsigned long long u64;

__device__ __forceinline__ void fma2(u64& a, u64 x, u64 p) {
    asm("fma.rn.f32x2 %0, %1, %2, %0;" : "+l"(a) : "l"(x), "l"(p));
}
__device__ __forceinline__ u64 add2(u64 a, u64 b) {
    u64 r; asm("add.rn.f32x2 %0, %1, %2;" : "=l"(r) : "l"(a), "l"(b)); return r;
}
__device__ __forceinline__ u64 pack2(float lo, float hi) {
    u64 r; asm("mov.b64 %0, {%1, %2};" : "=l"(r) : "f"(lo), "f"(hi)); return r;
}

__global__ __launch_bounds__(128, 1)
void crf_fwd_kernel(const float* __restrict__ y,
                    const float* __restrict__ mask,
                    const float* __restrict__ trans,
                    float* __restrict__ out,
                    int T) {
    const int b    = blockIdx.x;
    const int i    = threadIdx.x;      // 0..127 : output state
    const int lane = i & 31;
    const int warp = i >> 5;

    __shared__ __align__(16) float    pbuf[2][KDIM];
    __shared__ __align__(16) unsigned wmax[2][4];
    __shared__ float redf[4];
    __shared__ int   len_sh;

    // ---- one-time: E row = exp(trans[i][:]) as 64 packed f32x2 regs ----
    u64 E2[64];
    {
        const float4* t4 = reinterpret_cast<const float4*>(trans + (size_t)i * KDIM);
        #pragma unroll
        for (int q = 0; q < 32; q++) {
            float4 v = t4[q];
            E2[2*q]   = pack2(expf(v.x), expf(v.y));
            E2[2*q+1] = pack2(expf(v.z), expf(v.w));
        }
    }

    // ---- init state, renorm buffer, length ----
    if (i == 0) len_sh = 0;
    pbuf[0][i] = (i == 2) ? 1.0f : 0.0f;          // SOS_IDX = 2
    if (i < 4) wmax[0][i] = 0x3f800000u;          // Z_0 = 1.0
    __syncthreads();
    {
        const float* mb = mask + (size_t)b * T;
        int cnt = 0;
        for (int t = i; t < T; t += KDIM) cnt += (mb[t] != 0.0f);
        cnt = __reduce_add_sync(0xffffffffu, cnt);
        if (lane == 0) atomicAdd(&len_sh, cnt);
    }
    __syncthreads();
    const int len = len_sh;

    // ---- y prefetch pipeline (3 deep), pointer-increment ----
    const float* yb   = y + (size_t)b * T * KDIM + i;
    const float* yp   = yb + 3 * KDIM;
    const float* yend = yb + (size_t)T * KDIM;
    float ey = 0.0f, y1 = 0.0f, y2 = 0.0f;
    if (len > 0) ey = __expf(yb[0]);
    if (1 < T)   y1 = yb[KDIM];
    if (2 < T)   y2 = yb[2 * KDIM];

    int cur  = 0;
    int eacc = 0;

    for (int t = 0; t < len; t++) {
        // Z_t from previous step's per-warp maxima; fold into ey early so the
        // post-matvec tail has a single multiply. All off the matvec path.
        uint4 wm4 = *reinterpret_cast<const uint4*>(wmax[cur]);
        unsigned mbits = max(max(wm4.x, wm4.y), max(wm4.z, wm4.w));
        int Ee      = (int)(mbits >> 23);
        float rz    = __uint_as_float((unsigned)(254 - Ee) << 23); // 2^(127-Ee)
        float eyrz  = ey * rz;
        eacc       += Ee - 127;

        // matvec: q_i = sum_j E[i][j] * s_t[j]  (32x LDS.128 + 64x fma.f32x2,
        // 8 independent accumulator chains)
        const ulonglong2* p2 = reinterpret_cast<const ulonglong2*>(pbuf[cur]);
        u64 a0=0,a1=0,a2=0,a3=0,a4=0,a5=0,a6=0,a7=0;
        #pragma unroll
        for (int q = 0; q < 8; q++) {
            ulonglong2 v0 = p2[4*q+0];
            ulonglong2 v1 = p2[4*q+1];
            ulonglong2 v2 = p2[4*q+2];
            ulonglong2 v3 = p2[4*q+3];
            fma2(a0, E2[8*q+0], v0.x);
            fma2(a1, E2[8*q+1], v0.y);
            fma2(a2, E2[8*q+2], v1.x);
            fma2(a3, E2[8*q+3], v1.y);
            fma2(a4, E2[8*q+4], v2.x);
            fma2(a5, E2[8*q+5], v2.y);
            fma2(a6, E2[8*q+6], v3.x);
            fma2(a7, E2[8*q+7], v3.y);
        }
        u64 aa = add2(add2(add2(a0,a1), add2(a2,a3)),
                      add2(add2(a4,a5), add2(a6,a7)));
        float qlo, qhi;
        asm("mov.b64 {%0, %1}, %2;" : "=f"(qlo), "=f"(qhi) : "l"(aa));
        float s = (qlo + qhi) * eyrz;                // s >= 0 always

        // store first (drains during REDUX), then per-warp max bookkeeping
        pbuf[cur ^ 1][i] = s;
        unsigned wmv = __reduce_max_sync(0xffffffffu, __float_as_uint(s));
        if (lane == 0) wmax[cur ^ 1][warp] = wmv;

        // rotate y pipeline (off critical path)
        ey = __expf(y1);
        y1 = y2;
        y2 = (yp < yend) ? *yp : 0.0f;
        yp += KDIM;

        __syncthreads();
        cur ^= 1;
    }

    // ---- final: out[b] = log(sum_i s_i) + eacc*ln2 ----
    float e = pbuf[cur][i];
    e += __shfl_xor_sync(0xffffffffu, e, 16);
    e += __shfl_xor_sync(0xffffffffu, e, 8);
    e += __shfl_xor_sync(0xffffffffu, e, 4);
    e += __shfl_xor_sync(0xffffffffu, e, 2);
    e += __shfl_xor_sync(0xffffffffu, e, 1);
    if (lane == 0) redf[warp] = e;
    __syncthreads();
    if (i == 0) {
        float tot = (redf[0] + redf[1]) + (redf[2] + redf[3]);
        out[b] = logf(tot) + (float)((double)eacc * 0.6931471805599453);
    }
}

extern "C" void kernel_launch(void* const* d_in, const int* in_sizes, int n_in,
                              void* d_out, int out_size) {
    const float* y     = (const float*)d_in[0];   // (B, T, K) f32
    const float* mask  = (const float*)d_in[1];   // (B, T)    f32
    const float* trans = (const float*)d_in[2];   // (K, K)    f32
    float* out = (float*)d_out;                   // (B,)      f32

    const int B = out_size;                       // 64
    const int T = in_sizes[1] / B;                // 256

    crf_fwd_kernel<<<B, 128>>>(y, mask, trans, out, T);
}